// round 5
// baseline (speedup 1.0000x reference)
#include <cuda_runtime.h>
#include <math.h>
#include <stdint.h>

#define N_LEVELS   16
#define HASH_SIZE  (1u << 19)
#define HASH_MASK  (HASH_SIZE - 1u)
#define BLOCK      256
#define MAXN       (1 << 20)

// Morton binning: 5 bits/dim -> 2^15 buckets (avg 32 points/bucket at N=1M,
// i.e. one warp ~= one spatial cluster of side 1/32).
#define BPD        5
#define NB         (1 << (3 * BPD))

__device__ unsigned g_cnt[NB];
__device__ unsigned g_off[NB];
__device__ float4   g_pk[MAXN];   // (x, y, z, bitcast(original index)), permuted

struct Res16 { float r[N_LEVELS]; };

// ---------------------------------------------------------------------------

__device__ __forceinline__ unsigned morton_bucket(float px, float py, float pz) {
    unsigned cx = (unsigned)(px * 32.0f); cx = cx > 31u ? 31u : cx;
    unsigned cy = (unsigned)(py * 32.0f); cy = cy > 31u ? 31u : cy;
    unsigned cz = (unsigned)(pz * 32.0f); cz = cz > 31u ? 31u : cz;
    unsigned key = 0;
    #pragma unroll
    for (int b = 0; b < BPD; ++b) {
        key |= ((cx >> b) & 1u) << (3 * b)
             | ((cy >> b) & 1u) << (3 * b + 1)
             | ((cz >> b) & 1u) << (3 * b + 2);
    }
    return key;
}

__global__ void zero_cnt_kernel() {
    g_cnt[blockIdx.x * blockDim.x + threadIdx.x] = 0u;
}

// 4 points per thread, 3 coalesced float4 loads -> 4 independent atomics.
__global__ void hist_kernel(const float4* __restrict__ x4, int n) {
    const int t = blockIdx.x * blockDim.x + threadIdx.x;
    const int p0 = t * 4;
    if (p0 >= n) return;
    if (p0 + 3 < n) {
        const float4 a = x4[3 * t + 0];
        const float4 b = x4[3 * t + 1];
        const float4 c = x4[3 * t + 2];
        atomicAdd(&g_cnt[morton_bucket(a.x, a.y, a.z)], 1u);
        atomicAdd(&g_cnt[morton_bucket(a.w, b.x, b.y)], 1u);
        atomicAdd(&g_cnt[morton_bucket(b.z, b.w, c.x)], 1u);
        atomicAdd(&g_cnt[morton_bucket(c.y, c.z, c.w)], 1u);
    } else {
        const float* xf = reinterpret_cast<const float*>(x4);
        for (int p = p0; p < n; ++p)
            atomicAdd(&g_cnt[morton_bucket(xf[3*p], xf[3*p+1], xf[3*p+2])], 1u);
    }
}

// Single-block vectorized exclusive scan: 1024 threads x 32 buckets (8 uint4).
__global__ __launch_bounds__(1024) void scan_kernel() {
    __shared__ unsigned s[1024];
    const int t = threadIdx.x;
    const uint4* c4 = reinterpret_cast<const uint4*>(g_cnt);
    uint4* o4 = reinterpret_cast<uint4*>(g_off);

    uint4 v[8];
    unsigned sum = 0;
    #pragma unroll
    for (int k = 0; k < 8; ++k) {
        v[k] = c4[t * 8 + k];
        sum += v[k].x + v[k].y + v[k].z + v[k].w;
    }
    s[t] = sum;
    __syncthreads();

    for (int off = 1; off < 1024; off <<= 1) {
        unsigned u = (t >= off) ? s[t - off] : 0u;
        __syncthreads();
        s[t] += u;
        __syncthreads();
    }

    unsigned run = s[t] - sum;
    #pragma unroll
    for (int k = 0; k < 8; ++k) {
        uint4 o;
        o.x = run; run += v[k].x;
        o.y = run; run += v[k].y;
        o.z = run; run += v[k].z;
        o.w = run; run += v[k].w;
        o4[t * 8 + k] = o;
    }
}

__device__ __forceinline__ void scatter_one(float px, float py, float pz, unsigned j) {
    unsigned b = morton_bucket(px, py, pz);
    unsigned p = atomicAdd(&g_off[b], 1u);
    float4 v;
    v.x = px; v.y = py; v.z = pz; v.w = __uint_as_float(j);
    g_pk[p] = v;
}

// 4 points per thread for ILP on the atomic->STG.128 chains.
__global__ void scatter_kernel(const float4* __restrict__ x4, int n) {
    const int t = blockIdx.x * blockDim.x + threadIdx.x;
    const int p0 = t * 4;
    if (p0 >= n) return;
    if (p0 + 3 < n) {
        const float4 a = x4[3 * t + 0];
        const float4 b = x4[3 * t + 1];
        const float4 c = x4[3 * t + 2];
        scatter_one(a.x, a.y, a.z, p0 + 0);
        scatter_one(a.w, b.x, b.y, p0 + 1);
        scatter_one(b.z, b.w, c.x, p0 + 2);
        scatter_one(c.y, c.z, c.w, p0 + 3);
    } else {
        const float* xf = reinterpret_cast<const float*>(x4);
        for (int p = p0; p < n; ++p)
            scatter_one(xf[3*p], xf[3*p+1], xf[3*p+2], p);
    }
}

// ---------------------------------------------------------------------------

__device__ __forceinline__ float2 lerp2(float2 a, float2 b, float t) {
    float2 o;
    o.x = fmaf(t, b.x - a.x, a.x);
    o.y = fmaf(t, b.y - a.y, a.y);
    return o;
}

__global__ __launch_bounds__(BLOCK, 5) void hash_encode_kernel(
    const float* __restrict__ tables,
    float* __restrict__ out,
    Res16 rp, int n)
{
    __shared__ float    s_acc[BLOCK * 33];   // staged output rows (pad 33)
    __shared__ unsigned sperm[BLOCK];

    const int base = blockIdx.x * BLOCK;
    const int t = threadIdx.x;
    const int nblk = min(BLOCK, n - base);
    const int j = base + t;

    if (t < nblk) {
        const float4 pk = g_pk[j];           // coalesced LDG.128
        const float px = pk.x, py = pk.y, pz = pk.z;
        sperm[t] = __float_as_uint(pk.w);
        float* myrow = &s_acc[t * 33];

        #pragma unroll
        for (int L = 0; L < N_LEVELS; ++L) {
            const float res = rp.r[L];
            const float sx = px * res;
            const float sy = py * res;
            const float sz = pz * res;
            const int ix = (int)sx;          // trunc == floor for x >= 0
            const int iy = (int)sy;
            const int iz = (int)sz;
            const float fx = sx - (float)ix;
            const float fy = sy - (float)iy;
            const float fz = sz - (float)iz;

            const unsigned ux0 = (unsigned)ix;
            const unsigned ux1 = ux0 + 1u;
            const unsigned hy0 = (unsigned)iy * 2654435761u;
            const unsigned hy1 = hy0 + 2654435761u;
            const unsigned hz0 = (unsigned)iz * 805459861u;
            const unsigned hz1 = hz0 + 805459861u;

            const unsigned c00 = ux0 ^ hy0;
            const unsigned c10 = ux1 ^ hy0;
            const unsigned c01 = ux0 ^ hy1;
            const unsigned c11 = ux1 ^ hy1;

            const float2* __restrict__ tab =
                reinterpret_cast<const float2*>(tables) + (size_t)L * HASH_SIZE;

            const float2 f000 = __ldg(tab + ((c00 ^ hz0) & HASH_MASK));
            const float2 f100 = __ldg(tab + ((c10 ^ hz0) & HASH_MASK));
            const float2 f010 = __ldg(tab + ((c01 ^ hz0) & HASH_MASK));
            const float2 f110 = __ldg(tab + ((c11 ^ hz0) & HASH_MASK));
            const float2 f001 = __ldg(tab + ((c00 ^ hz1) & HASH_MASK));
            const float2 f101 = __ldg(tab + ((c10 ^ hz1) & HASH_MASK));
            const float2 f011 = __ldg(tab + ((c01 ^ hz1) & HASH_MASK));
            const float2 f111 = __ldg(tab + ((c11 ^ hz1) & HASH_MASK));

            const float2 v00 = lerp2(f000, f100, fx);
            const float2 v10 = lerp2(f010, f110, fx);
            const float2 v01 = lerp2(f001, f101, fx);
            const float2 v11 = lerp2(f011, f111, fx);
            const float2 w0  = lerp2(v00, v10, fy);
            const float2 w1  = lerp2(v01, v11, fy);
            const float2 rr  = lerp2(w0, w1, fz);

            myrow[2 * L + 0] = rr.x;     // direct to smem; no acc[] registers
            myrow[2 * L + 1] = rr.y;
        }
    }
    __syncthreads();

    // transpose store: each row (point) is exactly one 128B line in out.
    const int wid  = t >> 5;
    const int lane = t & 31;
    const int rend = min((wid + 1) * 32, nblk);
    for (int r = wid * 32; r < rend; ++r) {
        const size_t i = (size_t)sperm[r];
        out[i * (2 * N_LEVELS) + lane] = s_acc[r * 33 + lane];
    }
}

// ---------------------------------------------------------------------------

extern "C" void kernel_launch(void* const* d_in, const int* in_sizes, int n_in,
                              void* d_out, int out_size) {
    const float* x      = (const float*)d_in[0];
    const float* tables = (const float*)d_in[1];
    float* out          = (float*)d_out;

    const int n = in_sizes[0] / 3;

    // Resolutions exactly as the reference computes them.
    Res16 rp;
    const double growth = pow(512.0 / 16.0, 1.0 / (double)(N_LEVELS - 1));
    for (int l = 0; l < N_LEVELS; ++l) {
        double r = 16.0 * pow(growth, (double)l);
        rp.r[l] = (float)(long long)r;
    }

    const int blocks  = (n + BLOCK - 1) / BLOCK;
    const int blocks4 = (n / 4 + BLOCK - 1) / BLOCK + 1;   // 4 pts/thread kernels

    zero_cnt_kernel<<<NB / 1024, 1024>>>();
    hist_kernel<<<blocks4, BLOCK>>>(reinterpret_cast<const float4*>(x), n);
    scan_kernel<<<1, 1024>>>();
    scatter_kernel<<<blocks4, BLOCK>>>(reinterpret_cast<const float4*>(x), n);
    hash_encode_kernel<<<blocks, BLOCK>>>(tables, out, rp, n);
}

// round 6
// speedup vs baseline: 1.0438x; 1.0438x over previous
#include <cuda_runtime.h>
#include <math.h>
#include <stdint.h>

#define N_LEVELS   16
#define HASH_SIZE  (1u << 19)
#define HASH_MASK  (HASH_SIZE - 1u)
#define BLOCK      256
#define MAXN       (1 << 20)

// Morton binning: 5 bits/dim -> 2^15 buckets (avg 32 points/bucket at N=1M).
#define BPD        5
#define NB         (1 << (3 * BPD))

__device__ unsigned g_cnt[NB];
__device__ unsigned g_off[NB];
__device__ float4   g_pk[MAXN];   // (x, y, z, bitcast(original index)), permuted

struct Res16 { float r[N_LEVELS]; };

// ---------------------------------------------------------------------------

__device__ __forceinline__ unsigned morton_bucket(float px, float py, float pz) {
    unsigned cx = (unsigned)(px * 32.0f); cx = cx > 31u ? 31u : cx;
    unsigned cy = (unsigned)(py * 32.0f); cy = cy > 31u ? 31u : cy;
    unsigned cz = (unsigned)(pz * 32.0f); cz = cz > 31u ? 31u : cz;
    unsigned key = 0;
    #pragma unroll
    for (int b = 0; b < BPD; ++b) {
        key |= ((cx >> b) & 1u) << (3 * b)
             | ((cy >> b) & 1u) << (3 * b + 1)
             | ((cz >> b) & 1u) << (3 * b + 2);
    }
    return key;
}

__global__ void zero_cnt_kernel() {
    g_cnt[blockIdx.x * blockDim.x + threadIdx.x] = 0u;
}

// 4 points per thread, 3 coalesced float4 loads -> 4 independent atomics.
__global__ void hist_kernel(const float4* __restrict__ x4, int n) {
    const int t = blockIdx.x * blockDim.x + threadIdx.x;
    const int p0 = t * 4;
    if (p0 >= n) return;
    if (p0 + 3 < n) {
        const float4 a = x4[3 * t + 0];
        const float4 b = x4[3 * t + 1];
        const float4 c = x4[3 * t + 2];
        atomicAdd(&g_cnt[morton_bucket(a.x, a.y, a.z)], 1u);
        atomicAdd(&g_cnt[morton_bucket(a.w, b.x, b.y)], 1u);
        atomicAdd(&g_cnt[morton_bucket(b.z, b.w, c.x)], 1u);
        atomicAdd(&g_cnt[morton_bucket(c.y, c.z, c.w)], 1u);
    } else {
        const float* xf = reinterpret_cast<const float*>(x4);
        for (int p = p0; p < n; ++p)
            atomicAdd(&g_cnt[morton_bucket(xf[3*p], xf[3*p+1], xf[3*p+2])], 1u);
    }
}

// Single-block vectorized exclusive scan: 1024 threads x 32 buckets (8 uint4).
__global__ __launch_bounds__(1024) void scan_kernel() {
    __shared__ unsigned s[1024];
    const int t = threadIdx.x;
    const uint4* c4 = reinterpret_cast<const uint4*>(g_cnt);
    uint4* o4 = reinterpret_cast<uint4*>(g_off);

    uint4 v[8];
    unsigned sum = 0;
    #pragma unroll
    for (int k = 0; k < 8; ++k) {
        v[k] = c4[t * 8 + k];
        sum += v[k].x + v[k].y + v[k].z + v[k].w;
    }
    s[t] = sum;
    __syncthreads();

    for (int off = 1; off < 1024; off <<= 1) {
        unsigned u = (t >= off) ? s[t - off] : 0u;
        __syncthreads();
        s[t] += u;
        __syncthreads();
    }

    unsigned run = s[t] - sum;
    #pragma unroll
    for (int k = 0; k < 8; ++k) {
        uint4 o;
        o.x = run; run += v[k].x;
        o.y = run; run += v[k].y;
        o.z = run; run += v[k].z;
        o.w = run; run += v[k].w;
        o4[t * 8 + k] = o;
    }
}

__device__ __forceinline__ void scatter_one(float px, float py, float pz, unsigned j) {
    unsigned b = morton_bucket(px, py, pz);
    unsigned p = atomicAdd(&g_off[b], 1u);
    float4 v;
    v.x = px; v.y = py; v.z = pz; v.w = __uint_as_float(j);
    g_pk[p] = v;
}

__global__ void scatter_kernel(const float4* __restrict__ x4, int n) {
    const int t = blockIdx.x * blockDim.x + threadIdx.x;
    const int p0 = t * 4;
    if (p0 >= n) return;
    if (p0 + 3 < n) {
        const float4 a = x4[3 * t + 0];
        const float4 b = x4[3 * t + 1];
        const float4 c = x4[3 * t + 2];
        scatter_one(a.x, a.y, a.z, p0 + 0);
        scatter_one(a.w, b.x, b.y, p0 + 1);
        scatter_one(b.z, b.w, c.x, p0 + 2);
        scatter_one(c.y, c.z, c.w, p0 + 3);
    } else {
        const float* xf = reinterpret_cast<const float*>(x4);
        for (int p = p0; p < n; ++p)
            scatter_one(xf[3*p], xf[3*p+1], xf[3*p+2], p);
    }
}

// ---------------------------------------------------------------------------

__device__ __forceinline__ float2 lerp2(float2 a, float2 b, float t) {
    float2 o;
    o.x = fmaf(t, b.x - a.x, a.x);
    o.y = fmaf(t, b.y - a.y, a.y);
    return o;
}

__global__ __launch_bounds__(BLOCK) void hash_encode_kernel(
    const float* __restrict__ tables,
    float* __restrict__ out,
    Res16 rp, int n)
{
    __shared__ float    s_acc[BLOCK * 33];   // staged output rows (pad 33)
    __shared__ unsigned sperm[BLOCK];

    const int base = blockIdx.x * BLOCK;
    const int t = threadIdx.x;
    const int nblk = min(BLOCK, n - base);
    const int j = base + t;

    if (t < nblk) {
        const float4 pk = g_pk[j];           // coalesced LDG.128
        const float px = pk.x, py = pk.y, pz = pk.z;
        sperm[t] = __float_as_uint(pk.w);
        float* myrow = &s_acc[t * 33];

        // two passes of 8 levels; acc[16] in registers per pass, one flush each
        #pragma unroll
        for (int P = 0; P < 2; ++P) {
            float acc[N_LEVELS];   // 16 floats = 8 levels x 2 feats

            #pragma unroll
            for (int l = 0; l < 8; ++l) {
                const int L = P * 8 + l;
                const float res = rp.r[L];
                const float sx = px * res;
                const float sy = py * res;
                const float sz = pz * res;
                const int ix = (int)sx;      // trunc == floor for x >= 0
                const int iy = (int)sy;
                const int iz = (int)sz;
                const float fx = sx - (float)ix;
                const float fy = sy - (float)iy;
                const float fz = sz - (float)iz;

                const unsigned ux0 = (unsigned)ix;
                const unsigned ux1 = ux0 + 1u;
                const unsigned hy0 = (unsigned)iy * 2654435761u;
                const unsigned hy1 = hy0 + 2654435761u;
                const unsigned hz0 = (unsigned)iz * 805459861u;
                const unsigned hz1 = hz0 + 805459861u;

                const unsigned c00 = ux0 ^ hy0;
                const unsigned c10 = ux1 ^ hy0;
                const unsigned c01 = ux0 ^ hy1;
                const unsigned c11 = ux1 ^ hy1;

                const float2* __restrict__ tab =
                    reinterpret_cast<const float2*>(tables) + (size_t)L * HASH_SIZE;

                const float2 f000 = __ldg(tab + ((c00 ^ hz0) & HASH_MASK));
                const float2 f100 = __ldg(tab + ((c10 ^ hz0) & HASH_MASK));
                const float2 f010 = __ldg(tab + ((c01 ^ hz0) & HASH_MASK));
                const float2 f110 = __ldg(tab + ((c11 ^ hz0) & HASH_MASK));
                const float2 f001 = __ldg(tab + ((c00 ^ hz1) & HASH_MASK));
                const float2 f101 = __ldg(tab + ((c10 ^ hz1) & HASH_MASK));
                const float2 f011 = __ldg(tab + ((c01 ^ hz1) & HASH_MASK));
                const float2 f111 = __ldg(tab + ((c11 ^ hz1) & HASH_MASK));

                const float2 v00 = lerp2(f000, f100, fx);
                const float2 v10 = lerp2(f010, f110, fx);
                const float2 v01 = lerp2(f001, f101, fx);
                const float2 v11 = lerp2(f011, f111, fx);
                const float2 w0  = lerp2(v00, v10, fy);
                const float2 w1  = lerp2(v01, v11, fy);
                const float2 rr  = lerp2(w0, w1, fz);

                acc[2 * l + 0] = rr.x;
                acc[2 * l + 1] = rr.y;
            }

            #pragma unroll
            for (int k = 0; k < 16; ++k) myrow[P * 16 + k] = acc[k];
        }
    }
    __syncthreads();

    // transpose store: each row (point) is exactly one 128B line in out.
    const int wid  = t >> 5;
    const int lane = t & 31;
    const int rend = min((wid + 1) * 32, nblk);
    for (int r = wid * 32; r < rend; ++r) {
        const size_t i = (size_t)sperm[r];
        out[i * (2 * N_LEVELS) + lane] = s_acc[r * 33 + lane];
    }
}

// ---------------------------------------------------------------------------

extern "C" void kernel_launch(void* const* d_in, const int* in_sizes, int n_in,
                              void* d_out, int out_size) {
    const float* x      = (const float*)d_in[0];
    const float* tables = (const float*)d_in[1];
    float* out          = (float*)d_out;

    const int n = in_sizes[0] / 3;

    // Resolutions exactly as the reference computes them.
    Res16 rp;
    const double growth = pow(512.0 / 16.0, 1.0 / (double)(N_LEVELS - 1));
    for (int l = 0; l < N_LEVELS; ++l) {
        double r = 16.0 * pow(growth, (double)l);
        rp.r[l] = (float)(long long)r;
    }

    const int blocks  = (n + BLOCK - 1) / BLOCK;
    const int nq      = (n + 3) / 4;
    const int blocks4 = (nq + BLOCK - 1) / BLOCK;

    zero_cnt_kernel<<<NB / 1024, 1024>>>();
    hist_kernel<<<blocks4, BLOCK>>>(reinterpret_cast<const float4*>(x), n);
    scan_kernel<<<1, 1024>>>();
    scatter_kernel<<<blocks4, BLOCK>>>(reinterpret_cast<const float4*>(x), n);
    hash_encode_kernel<<<blocks, BLOCK>>>(tables, out, rp, n);
}